// round 14
// baseline (speedup 1.0000x reference)
#include <cuda_runtime.h>

// RawISPProcessing: demosaic (2x bilinear; reference's flips cancel exactly) +
// fused channel-flip/awb/ccm 3x3 matrix (incl. the *2) + gamma, for pred & gt.
//
// R14: packed-f32x2 kernel with column re-pairing (0,2)/(1,3):
//  - h-lerp base M = raw LDG.64 reinterpreted as u64 (zero-pack), 2 pk/plane
//  - lane-uniform green masks (odd-row lo half is gb verbatim)
//  - shared-sub v-lerps: one sub2 feeds both output rows (3 ops/quantity)
// Output permutation is free: unpack is already scalar at gamma/store time.

#define HIN  512
#define WIN  512
#define PLANE (HIN * WIN)
#define OPLANE (1024 * 1024)
#define R_ROWS 4

typedef unsigned long long u64;

#define C025 0x3E8000003E800000ULL   // (0.25f, 0.25f)
#define C075 0x3F4000003F400000ULL   // (0.75f, 0.75f)
#define C05  0x3F0000003F000000ULL   // (0.5f,  0.5f)

__device__ __forceinline__ u64 pk(float lo, float hi) {
    u64 r; asm("mov.b64 %0, {%1, %2};" : "=l"(r) : "f"(lo), "f"(hi)); return r;
}
__device__ __forceinline__ void upk(u64 v, float& lo, float& hi) {
    asm("mov.b64 {%0, %1}, %2;" : "=f"(lo), "=f"(hi) : "l"(v));
}
__device__ __forceinline__ u64 fma2(u64 a, u64 b, u64 c) {
    u64 r; asm("fma.rn.f32x2 %0, %1, %2, %3;" : "=l"(r) : "l"(a), "l"(b), "l"(c)); return r;
}
__device__ __forceinline__ u64 mul2(u64 a, u64 b) {
    u64 r; asm("mul.rn.f32x2 %0, %1, %2;" : "=l"(r) : "l"(a), "l"(b)); return r;
}
__device__ __forceinline__ u64 add2(u64 a, u64 b) {
    u64 r; asm("add.rn.f32x2 %0, %1, %2;" : "=l"(r) : "l"(a), "l"(b)); return r;
}
__device__ __forceinline__ u64 sub2(u64 a, u64 b) {
    u64 r; asm("sub.rn.f32x2 %0, %1, %2;" : "=l"(r) : "l"(a), "l"(b)); return r;
}

// 0.25*a + 0.75*b  =  b + 0.25*(a-b)
__device__ __forceinline__ u64 lerpE2(u64 a, u64 b) {
    return fma2(sub2(a, b), C025, b);
}
// 0.75*a + 0.25*b  =  a + 0.25*(b-a)
__device__ __forceinline__ u64 lerpO2(u64 a, u64 b) {
    return fma2(sub2(b, a), C025, a);
}

__device__ __forceinline__ float gamma_pow(float v) {
    float l;
    asm("lg2.approx.f32 %0, %1;" : "=f"(l) : "f"(v));
    l *= 0.45454545454545453f;   // 1/2.2
    float r;
    asm("ex2.approx.f32 %0, %1;" : "=f"(r) : "f"(l));
    return r;
}

// Rolling state, packed, LANE PAIRING = (col0,col2) lo / (col1,col3) hi:
//   p[0],p[1] = R;  p[2],p[3] = dg = gr-gb;  p[4],p[5] = gb;  p[6],p[7] = B.
struct HL { u64 p[8]; };

// One plane, one row: M = (t1,t2) straight from a 64-bit load.
// lo = cols(0,2) = M + 0.25*((t0,t1)-M);  hi = cols(1,3) = M + 0.25*((t2,t3)-M)
__device__ __forceinline__ void hplane(const float* __restrict__ q,
                                       int wm, int w0, int wp2,
                                       u64& lo, u64& hi) {
    u64 M = *(const u64*)(q + w0);        // LDG.64: (t1, t2) packed for free
    float t1, t2;
    upk(M, t1, t2);
    u64 A = pk(q[wm], t1);                // (t0, t1)
    u64 B = pk(t2, q[wp2]);               // (t2, t3)
    lo = fma2(sub2(A, M), C025, M);
    hi = fma2(sub2(B, M), C025, M);
}

__device__ __forceinline__ HL hlerp(const float* __restrict__ p,
                                    int wm, int w0, int wp2) {
    HL h;
    hplane(p,             wm, w0, wp2, h.p[0], h.p[1]);   // R
    u64 grlo, grhi, gblo, gbhi;
    hplane(p + PLANE,     wm, w0, wp2, grlo, grhi);       // GR
    hplane(p + 2 * PLANE, wm, w0, wp2, gblo, gbhi);       // GB
    h.p[2] = sub2(grlo, gblo);
    h.p[3] = sub2(grhi, gbhi);
    h.p[4] = gblo;
    h.p[5] = gbhi;
    hplane(p + 3 * PLANE, wm, w0, wp2, h.p[6], h.p[7]);   // B
    return h;
}

// packed matvec + scalar gamma + one streaming STG.128 per channel.
// lo carries cols (0,2), hi carries cols (1,3): permute at the scalar stage.
__device__ __forceinline__ void emit_row(float* __restrict__ po, const u64* A2,
                                         u64 rlo, u64 rhi, u64 glo, u64 ghi,
                                         u64 blo, u64 bhi) {
#pragma unroll
    for (int c = 0; c < 3; c++) {
        u64 olo = fma2(A2[c], rlo, fma2(A2[3 + c], glo, mul2(A2[6 + c], blo)));
        u64 ohi = fma2(A2[c], rhi, fma2(A2[3 + c], ghi, mul2(A2[6 + c], bhi)));
        float x0, x2, x1, x3;
        upk(olo, x0, x2);
        upk(ohi, x1, x3);
        float4 o = make_float4(gamma_pow(x0), gamma_pow(x1),
                               gamma_pow(x2), gamma_pow(x3));
        __stcs((float4*)(po + c * OPLANE), o);
    }
}

// Emit BOTH rows of an advance from (ha, hb) with shared subs:
//   d = ha-hb; odd row = hb + 0.75d; even row = hb + 0.25d.
// Green: odd row: glo = gb, ghi = gb + 0.5*dg.
//        even row: glo = gb + 0.5*dg, ghi = gb + dg.
__device__ __forceinline__ void emit_pair(float* __restrict__ po, const u64* A2,
                                          const HL& ha, const HL& hb) {
    u64 od[8], ev[8];
#pragma unroll
    for (int q = 0; q < 8; q++) {
        u64 d = sub2(ha.p[q], hb.p[q]);
        od[q] = fma2(d, C075, hb.p[q]);
        ev[q] = fma2(d, C025, hb.p[q]);
    }
    // odd row (2r+1)
    emit_row(po, A2, od[0], od[1],
             od[4], fma2(od[3], C05, od[5]),
             od[6], od[7]);
    // even row (2r+2)
    emit_row(po + 1024, A2, ev[0], ev[1],
             fma2(ev[2], C05, ev[4]), add2(ev[3], ev[5]),
             ev[6], ev[7]);
}

__global__ __launch_bounds__(128)
void isp_kernel(const float* __restrict__ pred,
                const float* __restrict__ gt,
                const float* __restrict__ awb,
                const float* __restrict__ ccm,
                float* __restrict__ out) {
    const int cp = blockIdx.x * 32 + threadIdx.x;    // col-pair 0..255
    const int w0 = 2 * cp;                           // input col base
    const int strip = blockIdx.y * 4 + threadIdx.y;  // 0..127
    const int h0 = strip * R_ROWS;
    const int z = blockIdx.z;                        // which*8 + b
    const int b = z & 7;

    const float* __restrict__ img =
        ((z >> 3) ? gt : pred) + (size_t)b * (4 * PLANE);

    // fused matrix A[j*3+c] = 2 * sum_m awb[b,2-j,m] * ccm[b,m,2-c], packed.
    u64 A2[9];
    {
        const float* Aw = awb + b * 9;
        const float* Cm = ccm + b * 9;
#pragma unroll
        for (int j = 0; j < 3; j++)
#pragma unroll
            for (int c = 0; c < 3; c++) {
                float s = 0.0f;
#pragma unroll
                for (int m = 0; m < 3; m++)
                    s = fmaf(__ldg(Aw + (2 - j) * 3 + m),
                             __ldg(Cm + m * 3 + (2 - c)), s);
                float v = 2.0f * s;
                A2[j * 3 + c] = pk(v, v);
            }
    }

    const int wm  = max(w0 - 1, 0);
    const int wp2 = min(w0 + 2, WIN - 1);

    float* po = out + (size_t)z * (3 * (size_t)OPLANE)
                    + (size_t)(2 * h0) * 1024 + 4 * cp;

    const float* prow = img + h0 * WIN;
    HL ha = hlerp(img + max(h0 - 1, 0) * WIN, wm, w0, wp2);
    HL hb = hlerp(prow, wm, w0, wp2);

    // first row of strip: output row 2*h0 (even) from (h0-1, h0)
    {
        u64 ev[8];
#pragma unroll
        for (int q = 0; q < 8; q++) ev[q] = lerpE2(ha.p[q], hb.p[q]);
        emit_row(po, A2, ev[0], ev[1],
                 fma2(ev[2], C05, ev[4]), add2(ev[3], ev[5]),
                 ev[6], ev[7]);
    }
    po += 1024;

#pragma unroll
    for (int r = 0; r < R_ROWS - 1; r++) {
        prow += WIN;
        ha = hb;
        hb = hlerp(prow, wm, w0, wp2);
        emit_pair(po, A2, ha, hb);   // rows 2*(h0+r)+1 and 2*(h0+r)+2
        po += 2048;
    }

    // last row of strip: output row 2*h0+2R-1 (odd) from (h0+R-1, h0+R)
    ha = hb;
    hb = hlerp(img + min(h0 + R_ROWS, HIN - 1) * WIN, wm, w0, wp2);
    {
        u64 od[8];
#pragma unroll
        for (int q = 0; q < 8; q++) od[q] = lerpO2(ha.p[q], hb.p[q]);
        emit_row(po, A2, od[0], od[1],
                 od[4], fma2(od[3], C05, od[5]),
                 od[6], od[7]);
    }
}

extern "C" void kernel_launch(void* const* d_in, const int* in_sizes, int n_in,
                              void* d_out, int out_size) {
    const float* pred = (const float*)d_in[0];
    const float* gt   = (const float*)d_in[1];
    const float* awb  = (const float*)d_in[2];
    const float* ccm  = (const float*)d_in[3];
    // d_in[4] = rgb_gain: unused by the reference

    dim3 blk(32, 4);
    dim3 grd(8, 32, 16);   // 256 col-pairs x 128 strips x (2 images * 8 batches)
    isp_kernel<<<grd, blk>>>(pred, gt, awb, ccm, (float*)d_out);
}

// round 15
// speedup vs baseline: 1.0091x; 1.0091x over previous
#include <cuda_runtime.h>

// RawISPProcessing: demosaic (2x bilinear; reference's flips cancel exactly) +
// fused channel-flip/awb/ccm 3x3 matrix (incl. the *2) + gamma, for pred & gt.
//
// R15: best-of-breed packed-f32x2 stream + 16-blocks/SM geometry:
//  - R14's zero-pack hplane (M = raw LDG.64) and (0,2)/(1,3) lane pairing
//    with lane-uniform green masks
//  - R13's per-row emit (no double-live od/ev arrays)
//  - 64-thread blocks: 64 regs -> 16 blocks/SM -> 50% occ cap, finer tail

#define HIN  512
#define WIN  512
#define PLANE (HIN * WIN)
#define OPLANE (1024 * 1024)
#define R_ROWS 4

typedef unsigned long long u64;

#define C025 0x3E8000003E800000ULL   // (0.25f, 0.25f)
#define C05  0x3F0000003F000000ULL   // (0.5f,  0.5f)

__device__ __forceinline__ u64 pk(float lo, float hi) {
    u64 r; asm("mov.b64 %0, {%1, %2};" : "=l"(r) : "f"(lo), "f"(hi)); return r;
}
__device__ __forceinline__ void upk(u64 v, float& lo, float& hi) {
    asm("mov.b64 {%0, %1}, %2;" : "=f"(lo), "=f"(hi) : "l"(v));
}
__device__ __forceinline__ u64 fma2(u64 a, u64 b, u64 c) {
    u64 r; asm("fma.rn.f32x2 %0, %1, %2, %3;" : "=l"(r) : "l"(a), "l"(b), "l"(c)); return r;
}
__device__ __forceinline__ u64 mul2(u64 a, u64 b) {
    u64 r; asm("mul.rn.f32x2 %0, %1, %2;" : "=l"(r) : "l"(a), "l"(b)); return r;
}
__device__ __forceinline__ u64 add2(u64 a, u64 b) {
    u64 r; asm("add.rn.f32x2 %0, %1, %2;" : "=l"(r) : "l"(a), "l"(b)); return r;
}
__device__ __forceinline__ u64 sub2(u64 a, u64 b) {
    u64 r; asm("sub.rn.f32x2 %0, %1, %2;" : "=l"(r) : "l"(a), "l"(b)); return r;
}

// 0.25*a + 0.75*b  =  b + 0.25*(a-b)
__device__ __forceinline__ u64 lerpE2(u64 a, u64 b) {
    return fma2(sub2(a, b), C025, b);
}
// 0.75*a + 0.25*b  =  a + 0.25*(b-a)
__device__ __forceinline__ u64 lerpO2(u64 a, u64 b) {
    return fma2(sub2(b, a), C025, a);
}

__device__ __forceinline__ float gamma_pow(float v) {
    float l;
    asm("lg2.approx.f32 %0, %1;" : "=f"(l) : "f"(v));
    l *= 0.45454545454545453f;   // 1/2.2
    float r;
    asm("ex2.approx.f32 %0, %1;" : "=f"(r) : "f"(l));
    return r;
}

// Rolling state, packed, lane pairing (col0,col2) lo / (col1,col3) hi:
//   p[0],p[1] = R;  p[2],p[3] = dg = gr-gb;  p[4],p[5] = gb;  p[6],p[7] = B.
struct HL { u64 p[8]; };

// One plane, one row: M = (t1,t2) straight from a 64-bit load (zero-pack).
// lo = cols(0,2) = M + 0.25*((t0,t1)-M);  hi = cols(1,3) = M + 0.25*((t2,t3)-M)
__device__ __forceinline__ void hplane(const float* __restrict__ q,
                                       int wm, int w0, int wp2,
                                       u64& lo, u64& hi) {
    u64 M = *(const u64*)(q + w0);        // LDG.64: (t1, t2) packed for free
    float t1, t2;
    upk(M, t1, t2);
    u64 A = pk(q[wm], t1);                // (t0, t1)
    u64 B = pk(t2, q[wp2]);               // (t2, t3)
    lo = fma2(sub2(A, M), C025, M);
    hi = fma2(sub2(B, M), C025, M);
}

__device__ __forceinline__ HL hlerp(const float* __restrict__ p,
                                    int wm, int w0, int wp2) {
    HL h;
    hplane(p,             wm, w0, wp2, h.p[0], h.p[1]);   // R
    u64 grlo, grhi, gblo, gbhi;
    hplane(p + PLANE,     wm, w0, wp2, grlo, grhi);       // GR
    hplane(p + 2 * PLANE, wm, w0, wp2, gblo, gbhi);       // GB
    h.p[2] = sub2(grlo, gblo);
    h.p[3] = sub2(grhi, gbhi);
    h.p[4] = gblo;
    h.p[5] = gbhi;
    hplane(p + 3 * PLANE, wm, w0, wp2, h.p[6], h.p[7]);   // B
    return h;
}

// packed matvec + scalar gamma + one streaming STG.128 per channel.
// lo = cols (0,2), hi = cols (1,3): permutation folded into the scalar stage.
__device__ __forceinline__ void emit_row(float* __restrict__ po, const u64* A2,
                                         u64 rlo, u64 rhi, u64 glo, u64 ghi,
                                         u64 blo, u64 bhi) {
#pragma unroll
    for (int c = 0; c < 3; c++) {
        u64 olo = fma2(A2[c], rlo, fma2(A2[3 + c], glo, mul2(A2[6 + c], blo)));
        u64 ohi = fma2(A2[c], rhi, fma2(A2[3 + c], ghi, mul2(A2[6 + c], bhi)));
        float x0, x2, x1, x3;
        upk(olo, x0, x2);
        upk(ohi, x1, x3);
        float4 o = make_float4(gamma_pow(x0), gamma_pow(x1),
                               gamma_pow(x2), gamma_pow(x3));
        __stcs((float4*)(po + c * OPLANE), o);
    }
}

// Even output row: v = 0.25*ha + 0.75*hb.
// Green: glo (cols 0,2) = gb + 0.5*dg;  ghi (cols 1,3) = gb + dg = gr.
__device__ __forceinline__ void emit_even(float* __restrict__ po, const u64* A2,
                                          const HL& ha, const HL& hb) {
    u64 rlo = lerpE2(ha.p[0], hb.p[0]), rhi = lerpE2(ha.p[1], hb.p[1]);
    u64 dglo = lerpE2(ha.p[2], hb.p[2]), dghi = lerpE2(ha.p[3], hb.p[3]);
    u64 gblo = lerpE2(ha.p[4], hb.p[4]), gbhi = lerpE2(ha.p[5], hb.p[5]);
    u64 blo = lerpE2(ha.p[6], hb.p[6]), bhi = lerpE2(ha.p[7], hb.p[7]);
    emit_row(po, A2, rlo, rhi,
             fma2(dglo, C05, gblo), add2(dghi, gbhi),
             blo, bhi);
}

// Odd output row: v = 0.75*ha + 0.25*hb.
// Green: glo (cols 0,2) = gb;  ghi (cols 1,3) = gb + 0.5*dg.
__device__ __forceinline__ void emit_odd(float* __restrict__ po, const u64* A2,
                                         const HL& ha, const HL& hb) {
    u64 rlo = lerpO2(ha.p[0], hb.p[0]), rhi = lerpO2(ha.p[1], hb.p[1]);
    u64 dghi = lerpO2(ha.p[3], hb.p[3]);
    u64 gblo = lerpO2(ha.p[4], hb.p[4]), gbhi = lerpO2(ha.p[5], hb.p[5]);
    u64 blo = lerpO2(ha.p[6], hb.p[6]), bhi = lerpO2(ha.p[7], hb.p[7]);
    emit_row(po, A2, rlo, rhi,
             gblo, fma2(dghi, C05, gbhi),
             blo, bhi);
}

__global__ __launch_bounds__(64)
void isp_kernel(const float* __restrict__ pred,
                const float* __restrict__ gt,
                const float* __restrict__ awb,
                const float* __restrict__ ccm,
                float* __restrict__ out) {
    const int cp = blockIdx.x * 32 + threadIdx.x;    // col-pair 0..255
    const int w0 = 2 * cp;                           // input col base
    const int strip = blockIdx.y * 2 + threadIdx.y;  // 0..127
    const int h0 = strip * R_ROWS;
    const int z = blockIdx.z;                        // which*8 + b
    const int b = z & 7;

    const float* __restrict__ img =
        ((z >> 3) ? gt : pred) + (size_t)b * (4 * PLANE);

    // fused matrix A[j*3+c] = 2 * sum_m awb[b,2-j,m] * ccm[b,m,2-c], packed.
    u64 A2[9];
    {
        const float* Aw = awb + b * 9;
        const float* Cm = ccm + b * 9;
#pragma unroll
        for (int j = 0; j < 3; j++)
#pragma unroll
            for (int c = 0; c < 3; c++) {
                float s = 0.0f;
#pragma unroll
                for (int m = 0; m < 3; m++)
                    s = fmaf(__ldg(Aw + (2 - j) * 3 + m),
                             __ldg(Cm + m * 3 + (2 - c)), s);
                float v = 2.0f * s;
                A2[j * 3 + c] = pk(v, v);
            }
    }

    const int wm  = max(w0 - 1, 0);
    const int wp2 = min(w0 + 2, WIN - 1);

    float* po = out + (size_t)z * (3 * (size_t)OPLANE)
                    + (size_t)(2 * h0) * 1024 + 4 * cp;

    const float* prow = img + h0 * WIN;
    HL ha = hlerp(img + max(h0 - 1, 0) * WIN, wm, w0, wp2);
    HL hb = hlerp(prow, wm, w0, wp2);

    // first row of strip: output row 2*h0 (even) from (h0-1, h0)
    emit_even(po, A2, ha, hb);
    po += 1024;

#pragma unroll
    for (int r = 0; r < R_ROWS - 1; r++) {
        prow += WIN;
        ha = hb;
        hb = hlerp(prow, wm, w0, wp2);
        emit_odd(po, A2, ha, hb);          // row 2*(h0+r)+1
        emit_even(po + 1024, A2, ha, hb);  // row 2*(h0+r)+2
        po += 2048;
    }

    // last row of strip: output row 2*h0+2R-1 (odd) from (h0+R-1, h0+R)
    ha = hb;
    hb = hlerp(img + min(h0 + R_ROWS, HIN - 1) * WIN, wm, w0, wp2);
    emit_odd(po, A2, ha, hb);
}

extern "C" void kernel_launch(void* const* d_in, const int* in_sizes, int n_in,
                              void* d_out, int out_size) {
    const float* pred = (const float*)d_in[0];
    const float* gt   = (const float*)d_in[1];
    const float* awb  = (const float*)d_in[2];
    const float* ccm  = (const float*)d_in[3];
    // d_in[4] = rgb_gain: unused by the reference

    dim3 blk(32, 2);
    dim3 grd(8, 64, 16);   // 256 col-pairs x 128 strips x (2 images * 8 batches)
    isp_kernel<<<grd, blk>>>(pred, gt, awb, ccm, (float*)d_out);
}